// round 12
// baseline (speedup 1.0000x reference)
#include <cuda_runtime.h>
#include <cuda_fp16.h>
#include <math.h>
#include <stdint.h>

// Problem dims
#define T_  512
#define B_  64
#define E_  512
#define H_  1024
#define V_  256
#define G4  4096   // 4*H gate-interleaved: col n = 4*j + g

#define NCTA_STEP 128
#define BH  (B_ * H_)

// ---------------- scratch (device globals; allocation-free) ----------------
__device__ float g_bias[G4];
__device__ float g_c[B_ * H_];
__device__ unsigned g_arrive[NCTA_STEP];
__device__ unsigned g_bar_gen;

// fp16 operands (16B aligned)
__device__ __align__(16) __half g_Xf16[(size_t)T_ * B_ * E_];   // input_seq fp16
__device__ __align__(16) __half g_WxThi[G4 * E_];               // WxT[n][k] hi
__device__ __align__(16) __half g_WxTlo[G4 * E_];               // WxT[n][k] lo
__device__ __align__(16) __half g_WhThi[G4 * H_];               // WhT[n][k] hi
__device__ __align__(16) __half g_WhTlo[G4 * H_];               // WhT[n][k] lo
__device__ __align__(16) __half g_WoThi[V_ * H_];               // WoT[v][k] hi
__device__ __align__(16) __half g_WoTlo[V_ * H_];               // WoT[v][k] lo
__device__ __align__(16) __half g_h0hi[BH];
__device__ __align__(16) __half g_h0lo[BH];
__device__ __align__(16) __half g_Hshi[(size_t)T_ * BH];        // h_t fp16 hi (A for t+1, out-GEMM)
__device__ __align__(16) __half g_Hslo[(size_t)T_ * BH];        // h_t fp16 lo (final-h accuracy)

// ---------------- PTX helpers (plain-sm_100 legal) ----------------
__device__ __forceinline__ uint32_t smem_u32(const void* p) {
    uint32_t a;
    asm("{ .reg .u64 t; cvta.to.shared.u64 t, %1; cvt.u32.u64 %0, t; }" : "=r"(a) : "l"(p));
    return a;
}
#define SWZ128(o) ((o) ^ (((o) >> 3) & 0x70))

#define CP16(dst, src) \
    asm volatile("cp.async.cg.shared.global [%0], [%1], 16;" :: "r"(dst), "l"(src))
#define CP_COMMIT() asm volatile("cp.async.commit_group;" ::: "memory")
#define CP_WAIT1()  asm volatile("cp.async.wait_group 1;" ::: "memory")
#define CP_WAIT0()  asm volatile("cp.async.wait_group 0;" ::: "memory")

#define LDSM4(r, addr) \
    asm volatile("ldmatrix.sync.aligned.m8n8.x4.shared.b16 {%0,%1,%2,%3}, [%4];" \
        : "=r"((r)[0]), "=r"((r)[1]), "=r"((r)[2]), "=r"((r)[3]) : "r"(addr))

#define MMAF16(c, a, b0, b1) \
    asm volatile("mma.sync.aligned.m16n8k16.row.col.f32.f16.f16.f32 " \
        "{%0,%1,%2,%3}, {%4,%5,%6,%7}, {%8,%9}, {%0,%1,%2,%3};" \
        : "+f"((c)[0]), "+f"((c)[1]), "+f"((c)[2]), "+f"((c)[3]) \
        : "r"((a)[0]), "r"((a)[1]), "r"((a)[2]), "r"((a)[3]), "r"(b0), "r"(b1))

__device__ __forceinline__ void split_f16(float v, __half& hi, __half& lo) {
    hi = __float2half_rn(v);
    lo = __float2half_rn(v - __half2float(hi));
}

// ---------------- packs: smem-tiled transposes (coalesced both sides) ----------------
__global__ __launch_bounds__(256) void pack_gates_t(
    const float* __restrict__ Wf, const float* __restrict__ Wi,
    const float* __restrict__ Wo, const float* __restrict__ Wc)
{
    __shared__ float tile[4][32][33];
    const int tid = threadIdx.x;
    const int jt  = blockIdx.x & 31;          // j tile (H/32 = 32)
    const int kt  = blockIdx.x >> 5;          // k tile ((E+H)/32 = 48)
    const int k0  = kt * 32, j0 = jt * 32;

    const float* W[4] = {Wf, Wi, Wo, Wc};
    #pragma unroll
    for (int g = 0; g < 4; g++)
        #pragma unroll
        for (int i = 0; i < 4; i++) {
            int u = tid + i * 256;
            int r = u >> 5, c = u & 31;
            tile[g][r][c] = W[g][(size_t)(k0 + r) * H_ + j0 + c];
        }
    __syncthreads();

    const bool isWx = (k0 < E_);
    const int kb = isWx ? k0 : (k0 - E_);
    const int K  = isWx ? E_ : H_;
    __half* Dh = isWx ? g_WxThi : g_WhThi;
    __half* Dl = isWx ? g_WxTlo : g_WhTlo;

    #pragma unroll
    for (int i = 0; i < 16; i++) {
        int rowu = (tid >> 5) + i * 8;        // 0..127 output rows within tile
        int g  = rowu & 3;
        int jj = rowu >> 2;
        int kk = tid & 31;
        float v = tile[g][kk][jj];
        __half hi, lo;
        split_f16(v, hi, lo);
        size_t o = (size_t)((j0 + jj) * 4 + g) * K + kb + kk;
        Dh[o] = hi;
        Dl[o] = lo;
    }
}

// Wout [H][V] row-major -> WoT[v][k]
__global__ __launch_bounds__(256) void pack_wout_t(const float* __restrict__ Wout)
{
    __shared__ float tile[32][33];
    const int tid = threadIdx.x;
    const int vt  = blockIdx.x & 7;           // V/32 = 8
    const int kt  = blockIdx.x >> 3;          // H/32 = 32
    const int k0  = kt * 32, v0 = vt * 32;

    #pragma unroll
    for (int i = 0; i < 4; i++) {
        int u = tid + i * 256;
        int r = u >> 5, c = u & 31;
        tile[r][c] = Wout[(size_t)(k0 + r) * V_ + v0 + c];
    }
    __syncthreads();

    #pragma unroll
    for (int i = 0; i < 4; i++) {
        int u = tid + i * 256;
        int vv = u >> 5, kk = u & 31;
        float val = tile[kk][vv];
        __half hi, lo;
        split_f16(val, hi, lo);
        size_t o = (size_t)(v0 + vv) * H_ + k0 + kk;
        g_WoThi[o] = hi;
        g_WoTlo[o] = lo;
    }
}

__global__ void convert_x(const float* __restrict__ src, __half* __restrict__ dst, size_t n)
{
    size_t i = (size_t)blockIdx.x * blockDim.x + threadIdx.x;
    if (i < n) dst[i] = __float2half_rn(src[i]);
}

// ---------------- init state (+ bias pack + barrier reset) ----------------
__global__ void init_state(const float* __restrict__ hidden, const float* __restrict__ cell,
                           const float* __restrict__ bf, const float* __restrict__ bi,
                           const float* __restrict__ bo, const float* __restrict__ bc)
{
    int i = blockIdx.x * blockDim.x + threadIdx.x;
    if (i < BH) {
        __half hi, lo;
        split_f16(hidden[i], hi, lo);
        g_h0hi[i] = hi;
        g_h0lo[i] = lo;
        g_c[i]    = cell[i];
    }
    if (i < H_) {
        g_bias[i * 4 + 0] = bf[i];
        g_bias[i * 4 + 1] = bi[i];
        g_bias[i * 4 + 2] = bo[i];
        g_bias[i * 4 + 3] = bc[i];
    }
    if (i < NCTA_STEP) g_arrive[i] = 0;
    if (i == 0) g_bar_gen = 0;
}

// ---------------- fp16 2-term GEMM (out projection): C = A@Bhi^T + A@Blo^T + bias ----
#define STG2        49152     // A 16K | Bhi 16K | Blo 16K
#define O2_A        0
#define O2_BHI      16384
#define O2_BLO      32768
#define GEMM_SMEM   (2 * STG2)

__device__ __forceinline__ void stage_fill2(
    uint32_t sstage, const __half* __restrict__ A,
    const __half* __restrict__ Bhi, const __half* __restrict__ Blo,
    int m0, int n0, int kc, int K, int tid)
{
    #pragma unroll
    for (int i = 0; i < 4; i++) {             // A: 128 rows x 8 cu
        int u  = tid + i * 256;
        int r  = u >> 3;
        int cu = u & 7;
        uint32_t dsw = SWZ128((uint32_t)(r * 128 + cu * 16));
        CP16(sstage + O2_A + dsw, A + (size_t)(m0 + r) * K + kc + cu * 8);
    }
    #pragma unroll
    for (int i = 0; i < 4; i++) {             // B: 128 rows x 8 cu
        int u  = tid + i * 256;
        int r  = u >> 3;
        int cu = u & 7;
        uint32_t dsw = SWZ128((uint32_t)(r * 128 + cu * 16));
        size_t bo = (size_t)(n0 + r) * K + kc + cu * 8;
        CP16(sstage + O2_BHI + dsw, Bhi + bo);
        CP16(sstage + O2_BLO + dsw, Blo + bo);
    }
}

__global__ __launch_bounds__(256, 2) void gemm_f16_2t(
    const __half* __restrict__ A,
    const __half* __restrict__ Bhi, const __half* __restrict__ Blo,
    const float* __restrict__ bias, float* __restrict__ C,
    int K, int ldc)
{
    extern __shared__ char smem[];
    const uint32_t sbase = smem_u32(smem);
    const int tid  = threadIdx.x;
    const int lane = tid & 31;
    const int w    = tid >> 5;
    const int wm   = w & 3;          // m offset wm*32
    const int wn   = w >> 2;         // n offset wn*64
    const int m0 = blockIdx.y * 128;
    const int n0 = blockIdx.x * 128;
    const int NC = K / 64;

    float acc[2][8][4];
    #pragma unroll
    for (int mt = 0; mt < 2; mt++)
        #pragma unroll
        for (int nt = 0; nt < 8; nt++)
            #pragma unroll
            for (int q = 0; q < 4; q++) acc[mt][nt][q] = 0.f;

    stage_fill2(sbase, A, Bhi, Blo, m0, n0, 0, K, tid);
    CP_COMMIT();

    const int a_row = (lane & 15);
    const int a_cuh = (lane >> 4);
    const int b_row = (lane & 7) + ((lane >> 4) << 3);
    const int b_cuh = ((lane >> 3) & 1);

    #pragma unroll 1
    for (int c = 0; c < NC; c++) {
        if (c + 1 < NC) {
            stage_fill2(sbase + ((c + 1) & 1) * STG2, A, Bhi, Blo,
                        m0, n0, (c + 1) * 64, K, tid);
            CP_COMMIT();
            CP_WAIT1();
        } else {
            CP_WAIT0();
        }
        __syncthreads();

        const uint32_t sS = sbase + (c & 1) * STG2;

        #pragma unroll
        for (int ks = 0; ks < 4; ks++) {
            uint32_t aF[2][4];
            #pragma unroll
            for (int mt = 0; mt < 2; mt++) {
                int row = wm * 32 + mt * 16 + a_row;
                int cu  = ks * 2 + a_cuh;
                uint32_t off = SWZ128((uint32_t)(row * 128 + cu * 16));
                LDSM4(aF[mt], sS + O2_A + off);
            }
            #pragma unroll
            for (int nh = 0; nh < 2; nh++) {
                uint32_t bH[2][4], bL[2][4];
                #pragma unroll
                for (int p = 0; p < 2; p++) {
                    int np = nh * 2 + p;
                    int row = wn * 64 + np * 16 + b_row;
                    int cu  = ks * 2 + b_cuh;
                    uint32_t off = SWZ128((uint32_t)(row * 128 + cu * 16));
                    LDSM4(bH[p], sS + O2_BHI + off);
                    LDSM4(bL[p], sS + O2_BLO + off);
                }
                #pragma unroll
                for (int mt = 0; mt < 2; mt++)
                    #pragma unroll
                    for (int p = 0; p < 2; p++) {
                        int np = nh * 2 + p;
                        MMAF16(acc[mt][2 * np],     aF[mt], bH[p][0], bH[p][1]);
                        MMAF16(acc[mt][2 * np + 1], aF[mt], bH[p][2], bH[p][3]);
                        MMAF16(acc[mt][2 * np],     aF[mt], bL[p][0], bL[p][1]);
                        MMAF16(acc[mt][2 * np + 1], aF[mt], bL[p][2], bL[p][3]);
                    }
            }
        }
        __syncthreads();
    }

    #pragma unroll
    for (int mt = 0; mt < 2; mt++) {
        int rbase = m0 + wm * 32 + mt * 16 + (lane >> 2);
        #pragma unroll
        for (int nt = 0; nt < 8; nt++) {
            int col = n0 + wn * 64 + nt * 8 + (lane & 3) * 2;
            float2 bv = *(const float2*)&bias[col];
            float2 v0, v1;
            v0.x = acc[mt][nt][0] + bv.x;
            v0.y = acc[mt][nt][1] + bv.y;
            v1.x = acc[mt][nt][2] + bv.x;
            v1.y = acc[mt][nt][3] + bv.y;
            *(float2*)&C[(size_t)rbase * ldc + col]       = v0;
            *(float2*)&C[(size_t)(rbase + 8) * ldc + col] = v1;
        }
    }
}

// ---------------- persistent fused LSTM: gates = [x_t, h_{t-1}] @ W ----------------
// 128 CTAs x 256 threads. CTA owns 32 gate-cols. Wx (64 KB) + Wh (128 KB) resident
// in smem; A streams x-chunks (4) then h-chunks (8), K = 1536, 12 chunks of 128.
// Contention-free barrier: per-CTA flags + CTA0 releaser. Bias from registers.
#define RB_HI       0                    // 96 KB: 24 k64-blocks (0-7 Wx, 8-23 Wh)
#define RB_LO       98304                // 96 KB
#define RA_BASE     196608               // 2 x 16 KB A stages
#define REC_SMEM    229376               // 224 KB

__global__ __launch_bounds__(256, 1) void lstm_mma_persistent()
{
    extern __shared__ char smem[];
    const uint32_t sbase = smem_u32(smem);

    const int tid  = threadIdx.x;
    const int lane = tid & 31;
    const int w    = tid >> 5;
    const int wm   = w & 1;          // m offset wm*32
    const int wn   = w >> 1;         // n offset wn*8
    const int n0   = blockIdx.x * 32;

    const int a_row = (lane & 15);
    const int a_cuh = (lane >> 4);
    const int b_row = (lane & 7);
    const int b_cu4 = ((lane >> 3) & 3);

    // ---- load resident Wx + Wh tiles (once) ----
    {
        int r = tid >> 3, cu = tid & 7;      // 256 threads = 32 rows x 8 cu
        uint32_t dswb = SWZ128((uint32_t)(r * 128 + cu * 16));
        #pragma unroll
        for (int blk = 0; blk < 8; blk++) {  // Wx blocks 0..7
            uint32_t d = (uint32_t)(blk * 4096) + dswb;
            size_t src = (size_t)(n0 + r) * E_ + blk * 64 + cu * 8;
            CP16(sbase + RB_HI + d, g_WxThi + src);
            CP16(sbase + RB_LO + d, g_WxTlo + src);
        }
        #pragma unroll
        for (int blk = 0; blk < 16; blk++) { // Wh blocks 8..23
            uint32_t d = (uint32_t)((blk + 8) * 4096) + dswb;
            size_t src = (size_t)(n0 + r) * H_ + blk * 64 + cu * 8;
            CP16(sbase + RB_HI + d, g_WhThi + src);
            CP16(sbase + RB_LO + d, g_WhTlo + src);
        }
        CP_COMMIT();
        CP_WAIT0();
    }
    __syncthreads();

    // epilogue ownership (fixed across steps)
    const int odd = lane & 1;
    const int ju  = (n0 >> 2) + wn * 2 + ((lane & 3) >> 1);   // hidden unit
    int eb[2];
    float cv[2];
    #pragma unroll
    for (int mt = 0; mt < 2; mt++) {
        eb[mt] = wm * 32 + mt * 16 + (lane >> 2) + (odd ? 8 : 0);
        cv[mt] = g_c[eb[mt] * H_ + ju];
    }
    const float4 bv = *(const float4*)&g_bias[ju * 4];

    // A-chunk issuer: chunk c of step with x base / h base
    auto issue_A = [&](int c, const __half* x_t, const __half* h_prev) {
        const __half* base;
        int stride, koff;
        if (c < 4) { base = x_t;    stride = E_; koff = c * 128; }
        else       { base = h_prev; stride = H_; koff = (c - 4) * 128; }
        uint32_t dstb = sbase + RA_BASE + (uint32_t)((c & 1) * 16384);
        #pragma unroll
        for (int i = 0; i < 4; i++) {
            int u = tid + i * 256;           // 0..1023
            int s = u >> 9;
            int rem = u & 511;
            int r = rem >> 3, cu = rem & 7;
            uint32_t dsw = (uint32_t)(s * 8192) + SWZ128((uint32_t)(r * 128 + cu * 16));
            CP16(dstb + dsw, base + (size_t)r * stride + koff + s * 64 + cu * 8);
        }
    };

    // prologue: chunk 0 of t=0 (x part)
    issue_A(0, g_Xf16, g_h0hi);
    CP_COMMIT();

    for (int t = 0; t < T_; t++) {
        const __half* x_t    = g_Xf16 + (size_t)t * B_ * E_;
        const __half* h_prev = (t == 0) ? g_h0hi : g_Hshi + (size_t)(t - 1) * BH;

        float accH[2][4], accL[2][4];
        #pragma unroll
        for (int mt = 0; mt < 2; mt++)
            #pragma unroll
            for (int q = 0; q < 4; q++) { accH[mt][q] = 0.f; accL[mt][q] = 0.f; }

        #pragma unroll 1
        for (int c = 0; c < 12; c++) {
            if (c + 1 < 12) {
                issue_A(c + 1, x_t, h_prev);
                CP_COMMIT();
                CP_WAIT1();
            } else {
                CP_WAIT0();
            }
            __syncthreads();

            const uint32_t sA = sbase + RA_BASE + (uint32_t)((c & 1) * 16384);

            #pragma unroll
            for (int s = 0; s < 2; s++) {
                const int blk = c * 2 + s;
                const uint32_t bHb = sbase + RB_HI + (uint32_t)(blk * 4096);
                const uint32_t bLb = sbase + RB_LO + (uint32_t)(blk * 4096);
                const uint32_t aB  = sA + (uint32_t)(s * 8192);

                #pragma unroll
                for (int ks2 = 0; ks2 < 2; ks2++) {
                    uint32_t bH[4], bL[4];
                    {
                        int row = wn * 8 + b_row;
                        int cu  = ks2 * 4 + b_cu4;
                        uint32_t off = SWZ128((uint32_t)(row * 128 + cu * 16));
                        LDSM4(bH, bHb + off);
                        LDSM4(bL, bLb + off);
                    }
                    #pragma unroll
                    for (int ks = 0; ks < 2; ks++) {
                        uint32_t aF[2][4];
                        #pragma unroll
                        for (int mt = 0; mt < 2; mt++) {
                            int row = wm * 32 + mt * 16 + a_row;
                            int cu  = ks2 * 4 + ks * 2 + a_cuh;
                            uint32_t off = SWZ128((uint32_t)(row * 128 + cu * 16));
                            LDSM4(aF[mt], aB + off);
                        }
                        #pragma unroll
                        for (int mt = 0; mt < 2; mt++) {
                            MMAF16(accH[mt], aF[mt], bH[2 * ks], bH[2 * ks + 1]);
                            MMAF16(accL[mt], aF[mt], bL[2 * ks], bL[2 * ks + 1]);
                        }
                    }
                }
            }
            __syncthreads();
        }

        // ---- fused epilogue: shuffle gate-quad exchange + LSTM pointwise ----
        #pragma unroll
        for (int mt = 0; mt < 2; mt++) {
            float v0 = accH[mt][0] + accL[mt][0];
            float v1 = accH[mt][1] + accL[mt][1];
            float v2 = accH[mt][2] + accL[mt][2];
            float v3 = accH[mt][3] + accL[mt][3];
            float e0 = __shfl_xor_sync(0xffffffffu, v0, 1);
            float e1 = __shfl_xor_sync(0xffffffffu, v1, 1);
            float e2 = __shfl_xor_sync(0xffffffffu, v2, 1);
            float e3 = __shfl_xor_sync(0xffffffffu, v3, 1);
            float pf = (odd ? e2 : v0) + bv.x;
            float pi = (odd ? e3 : v1) + bv.y;
            float po = (odd ? v2 : e0) + bv.z;
            float pc = (odd ? v3 : e1) + bv.w;
            float fg = 1.f / (1.f + expf(-pf));
            float ig = 1.f / (1.f + expf(-pi));
            float og = 1.f / (1.f + expf(-po));
            float ct = tanhf(pc);
            cv[mt] = fg * cv[mt] + ig * ct;
            float hnew = og * tanhf(cv[mt]);
            __half hhi, hlo;
            split_f16(hnew, hhi, hlo);
            size_t ho = (size_t)t * BH + (size_t)eb[mt] * H_ + ju;
            g_Hshi[ho] = hhi;
            g_Hslo[ho] = hlo;
        }

        // ---- barrier: release step t (contention-free) ----
        __threadfence();
        __syncthreads();
        if (t + 1 < T_) {
            issue_A(0, x_t + B_ * E_, h_prev);   // next step's x-chunk 0 (static data)
            CP_COMMIT();
        }
        if (tid == 0)
            ((volatile unsigned*)g_arrive)[blockIdx.x] = (unsigned)(t + 1);
        if (blockIdx.x == 0) {
            if (tid < 32) {
                for (;;) {
                    bool ok = true;
                    #pragma unroll
                    for (int q = 0; q < 4; q++)
                        if (((volatile unsigned*)g_arrive)[lane + q * 32] < (unsigned)(t + 1))
                            ok = false;
                    if (__all_sync(0xffffffffu, ok)) break;
                }
                __threadfence();
                if (tid == 0)
                    *((volatile unsigned*)&g_bar_gen) = (unsigned)(t + 1);
            }
        } else {
            if (tid == 0) {
                while (*((volatile unsigned*)&g_bar_gen) < (unsigned)(t + 1)) { }
            }
        }
        __syncthreads();
        __threadfence();
    }

    // write back cell state
    #pragma unroll
    for (int mt = 0; mt < 2; mt++)
        g_c[eb[mt] * H_ + ju] = cv[mt];
}

// ---------------- final h / c copy (hi+lo reconstruction) ----------------
__global__ void write_hc(float* __restrict__ dst)
{
    int i = blockIdx.x * blockDim.x + threadIdx.x;
    if (i < BH) {
        size_t o = (size_t)(T_ - 1) * BH + i;
        dst[i]      = __half2float(g_Hshi[o]) + __half2float(g_Hslo[o]);
        dst[BH + i] = g_c[i];
    }
}

// ---------------- launch ----------------
extern "C" void kernel_launch(void* const* d_in, const int* in_sizes, int n_in,
                              void* d_out, int out_size)
{
    const float* input_seq = (const float*)d_in[0];
    const float* hidden    = (const float*)d_in[1];
    const float* cell      = (const float*)d_in[2];
    const float* Wf        = (const float*)d_in[3];
    const float* bf        = (const float*)d_in[4];
    const float* Wi        = (const float*)d_in[5];
    const float* bi        = (const float*)d_in[6];
    const float* Wo        = (const float*)d_in[7];
    const float* bo        = (const float*)d_in[8];
    const float* Wc        = (const float*)d_in[9];
    const float* bc        = (const float*)d_in[10];
    const float* Wout      = (const float*)d_in[11];
    const float* bout      = (const float*)d_in[12];
    float* out = (float*)d_out;

    cudaFuncSetAttribute(gemm_f16_2t, cudaFuncAttributeMaxDynamicSharedMemorySize, GEMM_SMEM);
    cudaFuncSetAttribute(lstm_mma_persistent, cudaFuncAttributeMaxDynamicSharedMemorySize, REC_SMEM);

    __half *pXf, *pWoh, *pWol, *pHsh;
    cudaGetSymbolAddress((void**)&pXf,   g_Xf16);
    cudaGetSymbolAddress((void**)&pWoh,  g_WoThi);
    cudaGetSymbolAddress((void**)&pWol,  g_WoTlo);
    cudaGetSymbolAddress((void**)&pHsh,  g_Hshi);

    // 1. packs + conversions
    pack_gates_t<<<48 * 32, 256>>>(Wf, Wi, Wo, Wc);
    pack_wout_t<<<32 * 8, 256>>>(Wout);
    {
        size_t n = (size_t)T_ * B_ * E_;
        convert_x<<<(int)((n + 255) / 256), 256>>>(input_seq, pXf, n);
    }
    init_state<<<(BH + 255) / 256, 256>>>(hidden, cell, bf, bi, bo, bc);

    // 2. fused recurrence (x-projection folded in; no Xproj pass)
    lstm_mma_persistent<<<NCTA_STEP, 256, REC_SMEM>>>();

    // 3. out GEMM (M=32768, N=256, K=1024), fp16 2-term
    {
        dim3 grid(V_ / 128, (T_ * B_) / 128);
        gemm_f16_2t<<<grid, 256, GEMM_SMEM>>>(pHsh, pWoh, pWol, bout, out, H_, V_);
    }

    // 4. final h, c
    write_hc<<<(BH + 255) / 256, 256>>>(out + (size_t)T_ * B_ * V_);
}

// round 15
// speedup vs baseline: 1.0216x; 1.0216x over previous
#include <cuda_runtime.h>
#include <cuda_fp16.h>
#include <math.h>
#include <stdint.h>

// Problem dims
#define T_  512
#define B_  64
#define E_  512
#define H_  1024
#define V_  256
#define G4  4096   // 4*H gate-interleaved: col n = 4*j + g

#define NCTA_REC 256
#define BH  (B_ * H_)

// ---------------- scratch (device globals; allocation-free) ----------------
__device__ float g_bias[G4];
__device__ float g_Xproj[(size_t)T_ * B_ * G4];       // 512 MB
__device__ float g_c[B_ * H_];
__device__ __align__(16) unsigned g_arrive[NCTA_REC];
__device__ unsigned g_bar_gen;

// fp16 operands (16B aligned)
__device__ __align__(16) __half g_Xf16[(size_t)T_ * B_ * E_];   // input_seq fp16
__device__ __align__(16) __half g_WxThi[G4 * E_];               // WxT[n][k] hi
__device__ __align__(16) __half g_WxTlo[G4 * E_];               // WxT[n][k] lo
__device__ __align__(16) __half g_WhThi[G4 * H_];               // WhT[n][k] hi
__device__ __align__(16) __half g_WhTlo[G4 * H_];               // WhT[n][k] lo
__device__ __align__(16) __half g_WoThi[V_ * H_];               // WoT[v][k] hi
__device__ __align__(16) __half g_WoTlo[V_ * H_];               // WoT[v][k] lo
__device__ __align__(16) __half g_h0hi[BH];
__device__ __align__(16) __half g_h0lo[BH];
__device__ __align__(16) __half g_Hshi[(size_t)T_ * BH];        // h_t fp16 hi
__device__ __align__(16) __half g_Hslo[(size_t)T_ * BH];        // h_t fp16 lo

// ---------------- PTX helpers (plain-sm_100 legal) ----------------
__device__ __forceinline__ uint32_t smem_u32(const void* p) {
    uint32_t a;
    asm("{ .reg .u64 t; cvta.to.shared.u64 t, %1; cvt.u32.u64 %0, t; }" : "=r"(a) : "l"(p));
    return a;
}
#define SWZ128(o) ((o) ^ (((o) >> 3) & 0x70))

#define CP16(dst, src) \
    asm volatile("cp.async.cg.shared.global [%0], [%1], 16;" :: "r"(dst), "l"(src))
#define CP_COMMIT() asm volatile("cp.async.commit_group;" ::: "memory")
#define CP_WAIT1()  asm volatile("cp.async.wait_group 1;" ::: "memory")
#define CP_WAIT0()  asm volatile("cp.async.wait_group 0;" ::: "memory")

#define LDSM4(r, addr) \
    asm volatile("ldmatrix.sync.aligned.m8n8.x4.shared.b16 {%0,%1,%2,%3}, [%4];" \
        : "=r"((r)[0]), "=r"((r)[1]), "=r"((r)[2]), "=r"((r)[3]) : "r"(addr))

#define MMAF16(c, a, b0, b1) \
    asm volatile("mma.sync.aligned.m16n8k16.row.col.f32.f16.f16.f32 " \
        "{%0,%1,%2,%3}, {%4,%5,%6,%7}, {%8,%9}, {%0,%1,%2,%3};" \
        : "+f"((c)[0]), "+f"((c)[1]), "+f"((c)[2]), "+f"((c)[3]) \
        : "r"((a)[0]), "r"((a)[1]), "r"((a)[2]), "r"((a)[3]), "r"(b0), "r"(b1))

__device__ __forceinline__ void split_f16(float v, __half& hi, __half& lo) {
    hi = __float2half_rn(v);
    lo = __float2half_rn(v - __half2float(hi));
}

// ---------------- packs: smem-tiled transposes (coalesced both sides) ----------------
__global__ __launch_bounds__(256) void pack_gates_t(
    const float* __restrict__ Wf, const float* __restrict__ Wi,
    const float* __restrict__ Wo, const float* __restrict__ Wc)
{
    __shared__ float tile[4][32][33];
    const int tid = threadIdx.x;
    const int jt  = blockIdx.x & 31;          // j tile (H/32 = 32)
    const int kt  = blockIdx.x >> 5;          // k tile ((E+H)/32 = 48)
    const int k0  = kt * 32, j0 = jt * 32;

    const float* W[4] = {Wf, Wi, Wo, Wc};
    #pragma unroll
    for (int g = 0; g < 4; g++)
        #pragma unroll
        for (int i = 0; i < 4; i++) {
            int u = tid + i * 256;
            int r = u >> 5, c = u & 31;
            tile[g][r][c] = W[g][(size_t)(k0 + r) * H_ + j0 + c];
        }
    __syncthreads();

    const bool isWx = (k0 < E_);
    const int kb = isWx ? k0 : (k0 - E_);
    const int K  = isWx ? E_ : H_;
    __half* Dh = isWx ? g_WxThi : g_WhThi;
    __half* Dl = isWx ? g_WxTlo : g_WhTlo;

    #pragma unroll
    for (int i = 0; i < 16; i++) {
        int rowu = (tid >> 5) + i * 8;        // 0..127 output rows within tile
        int g  = rowu & 3;
        int jj = rowu >> 2;
        int kk = tid & 31;
        float v = tile[g][kk][jj];
        __half hi, lo;
        split_f16(v, hi, lo);
        size_t o = (size_t)((j0 + jj) * 4 + g) * K + kb + kk;
        Dh[o] = hi;
        Dl[o] = lo;
    }
}

// Wout [H][V] row-major -> WoT[v][k]
__global__ __launch_bounds__(256) void pack_wout_t(const float* __restrict__ Wout)
{
    __shared__ float tile[32][33];
    const int tid = threadIdx.x;
    const int vt  = blockIdx.x & 7;           // V/32 = 8
    const int kt  = blockIdx.x >> 3;          // H/32 = 32
    const int k0  = kt * 32, v0 = vt * 32;

    #pragma unroll
    for (int i = 0; i < 4; i++) {
        int u = tid + i * 256;
        int r = u >> 5, c = u & 31;
        tile[r][c] = Wout[(size_t)(k0 + r) * V_ + v0 + c];
    }
    __syncthreads();

    #pragma unroll
    for (int i = 0; i < 4; i++) {
        int u = tid + i * 256;
        int vv = u >> 5, kk = u & 31;
        float val = tile[kk][vv];
        __half hi, lo;
        split_f16(val, hi, lo);
        size_t o = (size_t)(v0 + vv) * H_ + k0 + kk;
        g_WoThi[o] = hi;
        g_WoTlo[o] = lo;
    }
}

__global__ void convert_x(const float* __restrict__ src, __half* __restrict__ dst, size_t n)
{
    size_t i = (size_t)blockIdx.x * blockDim.x + threadIdx.x;
    if (i < n) dst[i] = __float2half_rn(src[i]);
}

// ---------------- init state (+ bias pack + barrier reset) ----------------
__global__ void init_state(const float* __restrict__ hidden, const float* __restrict__ cell,
                           const float* __restrict__ bf, const float* __restrict__ bi,
                           const float* __restrict__ bo, const float* __restrict__ bc)
{
    int i = blockIdx.x * blockDim.x + threadIdx.x;
    if (i < BH) {
        __half hi, lo;
        split_f16(hidden[i], hi, lo);
        g_h0hi[i] = hi;
        g_h0lo[i] = lo;
        g_c[i]    = cell[i];
    }
    if (i < H_) {
        g_bias[i * 4 + 0] = bf[i];
        g_bias[i * 4 + 1] = bi[i];
        g_bias[i * 4 + 2] = bo[i];
        g_bias[i * 4 + 3] = bc[i];
    }
    if (i < NCTA_REC) g_arrive[i] = 0;
    if (i == 0) g_bar_gen = 0;
}

// ---------------- fp16 2-term GEMM: C = A@Bhi^T + A@Blo^T + bias ----------------
#define STG2        49152     // A 16K | Bhi 16K | Blo 16K
#define O2_A        0
#define O2_BHI      16384
#define O2_BLO      32768
#define GEMM_SMEM   (2 * STG2)

__device__ __forceinline__ void stage_fill2(
    uint32_t sstage, const __half* __restrict__ A,
    const __half* __restrict__ Bhi, const __half* __restrict__ Blo,
    int m0, int n0, int kc, int K, int tid)
{
    #pragma unroll
    for (int i = 0; i < 4; i++) {             // A: 128 rows x 8 cu
        int u  = tid + i * 256;
        int r  = u >> 3;
        int cu = u & 7;
        uint32_t dsw = SWZ128((uint32_t)(r * 128 + cu * 16));
        CP16(sstage + O2_A + dsw, A + (size_t)(m0 + r) * K + kc + cu * 8);
    }
    #pragma unroll
    for (int i = 0; i < 4; i++) {             // B: 128 rows x 8 cu
        int u  = tid + i * 256;
        int r  = u >> 3;
        int cu = u & 7;
        uint32_t dsw = SWZ128((uint32_t)(r * 128 + cu * 16));
        size_t bo = (size_t)(n0 + r) * K + kc + cu * 8;
        CP16(sstage + O2_BHI + dsw, Bhi + bo);
        CP16(sstage + O2_BLO + dsw, Blo + bo);
    }
}

__global__ __launch_bounds__(256, 2) void gemm_f16_2t(
    const __half* __restrict__ A,
    const __half* __restrict__ Bhi, const __half* __restrict__ Blo,
    const float* __restrict__ bias, float* __restrict__ C,
    int K, int ldc)
{
    extern __shared__ char smem[];
    const uint32_t sbase = smem_u32(smem);
    const int tid  = threadIdx.x;
    const int lane = tid & 31;
    const int w    = tid >> 5;
    const int wm   = w & 3;          // m offset wm*32
    const int wn   = w >> 2;         // n offset wn*64
    const int m0 = blockIdx.y * 128;
    const int n0 = blockIdx.x * 128;
    const int NC = K / 64;

    float acc[2][8][4];
    #pragma unroll
    for (int mt = 0; mt < 2; mt++)
        #pragma unroll
        for (int nt = 0; nt < 8; nt++)
            #pragma unroll
            for (int q = 0; q < 4; q++) acc[mt][nt][q] = 0.f;

    stage_fill2(sbase, A, Bhi, Blo, m0, n0, 0, K, tid);
    CP_COMMIT();

    const int a_row = (lane & 15);
    const int a_cuh = (lane >> 4);
    const int b_row = (lane & 7) + ((lane >> 4) << 3);
    const int b_cuh = ((lane >> 3) & 1);

    #pragma unroll 1
    for (int c = 0; c < NC; c++) {
        if (c + 1 < NC) {
            stage_fill2(sbase + ((c + 1) & 1) * STG2, A, Bhi, Blo,
                        m0, n0, (c + 1) * 64, K, tid);
            CP_COMMIT();
            CP_WAIT1();
        } else {
            CP_WAIT0();
        }
        __syncthreads();

        const uint32_t sS = sbase + (c & 1) * STG2;

        #pragma unroll
        for (int ks = 0; ks < 4; ks++) {
            uint32_t aF[2][4];
            #pragma unroll
            for (int mt = 0; mt < 2; mt++) {
                int row = wm * 32 + mt * 16 + a_row;
                int cu  = ks * 2 + a_cuh;
                uint32_t off = SWZ128((uint32_t)(row * 128 + cu * 16));
                LDSM4(aF[mt], sS + O2_A + off);
            }
            #pragma unroll
            for (int nh = 0; nh < 2; nh++) {
                uint32_t bH[2][4], bL[2][4];
                #pragma unroll
                for (int p = 0; p < 2; p++) {
                    int np = nh * 2 + p;
                    int row = wn * 64 + np * 16 + b_row;
                    int cu  = ks * 2 + b_cuh;
                    uint32_t off = SWZ128((uint32_t)(row * 128 + cu * 16));
                    LDSM4(bH[p], sS + O2_BHI + off);
                    LDSM4(bL[p], sS + O2_BLO + off);
                }
                #pragma unroll
                for (int mt = 0; mt < 2; mt++)
                    #pragma unroll
                    for (int p = 0; p < 2; p++) {
                        int np = nh * 2 + p;
                        MMAF16(acc[mt][2 * np],     aF[mt], bH[p][0], bH[p][1]);
                        MMAF16(acc[mt][2 * np + 1], aF[mt], bH[p][2], bH[p][3]);
                        MMAF16(acc[mt][2 * np],     aF[mt], bL[p][0], bL[p][1]);
                        MMAF16(acc[mt][2 * np + 1], aF[mt], bL[p][2], bL[p][3]);
                    }
            }
        }
        __syncthreads();
    }

    #pragma unroll
    for (int mt = 0; mt < 2; mt++) {
        int rbase = m0 + wm * 32 + mt * 16 + (lane >> 2);
        #pragma unroll
        for (int nt = 0; nt < 8; nt++) {
            int col = n0 + wn * 64 + nt * 8 + (lane & 3) * 2;
            float2 bv = *(const float2*)&bias[col];
            float2 v0, v1;
            v0.x = acc[mt][nt][0] + bv.x;
            v0.y = acc[mt][nt][1] + bv.y;
            v1.x = acc[mt][nt][2] + bv.x;
            v1.y = acc[mt][nt][3] + bv.y;
            *(float2*)&C[(size_t)rbase * ldc + col]       = v0;
            *(float2*)&C[(size_t)(rbase + 8) * ldc + col] = v1;
        }
    }
}

// ---------------- persistent tensor-core LSTM recurrence ----------------
// 256 CTAs x 256 threads, 2 CTAs/SM (96 KB each). CTA owns 16 gate-cols.
// Wh tile (64 KB hi+lo) smem-resident. 8 warps = 2m x 2n x 2k (K-split);
// cross-k reduction through 4 KB smem (reuses A stage 0). Epilogue: warps 0-3.
// Contention-free flag barrier with VOLATILE polling (round-12-proven pattern).
#define RB_HI       0                    // 32 KB: 16 k64-blocks x 2 KB (16 rows x 128B)
#define RB_LO       32768                // 32 KB
#define RA_BASE     65536                // 2 x 16 KB A stages (stage0 reused as red buf)
#define REC_SMEM    98304                // 96 KB

__global__ __launch_bounds__(256, 2) void lstm_mma_persistent()
{
    extern __shared__ char smem[];
    const uint32_t sbase = smem_u32(smem);
    float* red = (float*)(smem + RA_BASE);   // reused after last chunk

    const int tid  = threadIdx.x;
    const int lane = tid & 31;
    const int w    = tid >> 5;
    const int wk   = w >> 2;         // k-half 0/1
    const int wm   = (w >> 1) & 1;   // m offset wm*32
    const int wn   = w & 1;          // n offset wn*8
    const int n0   = blockIdx.x * 16;
    const int p    = wm * 2 + wn;    // (m,n) position 0..3

    const int a_row = (lane & 15);
    const int a_cuh = (lane >> 4);
    const int b_row = (lane & 7);
    const int b_cu4 = ((lane >> 3) & 3);

    // ---- load resident Wh tile (once): 16 rows x 1024 k, hi+lo ----
    if (tid < 128) {
        int r = tid >> 3, cu = tid & 7;
        uint32_t dswb = SWZ128((uint32_t)(r * 128 + cu * 16));
        #pragma unroll
        for (int blk = 0; blk < 16; blk++) {
            uint32_t d = (uint32_t)(blk * 2048) + dswb;
            size_t src = (size_t)(n0 + r) * H_ + blk * 64 + cu * 8;
            CP16(sbase + RB_HI + d, g_WhThi + src);
            CP16(sbase + RB_LO + d, g_WhTlo + src);
        }
    }
    CP_COMMIT();
    CP_WAIT0();
    __syncthreads();

    // epilogue ownership (warps 0-3 only; fixed across steps)
    const int odd = lane & 1;
    const int ju  = blockIdx.x * 4 + wn * 2 + ((lane & 3) >> 1);   // hidden unit
    int eb[2];
    float cv[2];
    #pragma unroll
    for (int mt = 0; mt < 2; mt++) {
        eb[mt] = wm * 32 + mt * 16 + (lane >> 2) + (odd ? 8 : 0);
        cv[mt] = g_c[eb[mt] * H_ + ju];
    }
    const unsigned FULL = 0xffffffffu;

    for (int t = 0; t < T_; t++) {
        const __half* A_t = (t == 0) ? g_h0hi : g_Hshi + (size_t)(t - 1) * BH;
        const float* xp_t = g_Xproj + (size_t)t * B_ * G4;

        // prefetch per-step epilogue operands (hidden under mainloop)
        float4 xpv[2];
        #pragma unroll
        for (int mt = 0; mt < 2; mt++)
            xpv[mt] = *(const float4*)&xp_t[(size_t)eb[mt] * G4 + ju * 4];

        float accH[2][4], accL[2][4];
        #pragma unroll
        for (int mt = 0; mt < 2; mt++)
            #pragma unroll
            for (int q = 0; q < 4; q++) { accH[mt][q] = 0.f; accL[mt][q] = 0.f; }

        // ---- prologue: fill A chunk 0 (k128 = 16 KB) ----
        #pragma unroll
        for (int i = 0; i < 4; i++) {
            int u = tid + i * 256;            // 0..1023
            int s = u >> 9;
            int rem = u & 511;
            int r = rem >> 3, cu = rem & 7;
            uint32_t dsw = (uint32_t)(s * 8192) + SWZ128((uint32_t)(r * 128 + cu * 16));
            CP16(sbase + RA_BASE + dsw, A_t + (size_t)r * H_ + s * 64 + cu * 8);
        }
        CP_COMMIT();

        #pragma unroll 1
        for (int c = 0; c < H_ / 128; c++) {
            if (c + 1 < H_ / 128) {
                uint32_t sN = sbase + RA_BASE + (uint32_t)(((c + 1) & 1) * 16384);
                int kc = (c + 1) * 128;
                #pragma unroll
                for (int i = 0; i < 4; i++) {
                    int u = tid + i * 256;
                    int s = u >> 9;
                    int rem = u & 511;
                    int r = rem >> 3, cu = rem & 7;
                    uint32_t dsw = (uint32_t)(s * 8192) + SWZ128((uint32_t)(r * 128 + cu * 16));
                    CP16(sN + dsw, A_t + (size_t)r * H_ + kc + s * 64 + cu * 8);
                }
                CP_COMMIT();
                CP_WAIT1();
            } else {
                CP_WAIT0();
            }
            __syncthreads();

            const uint32_t aB  = sbase + RA_BASE + (uint32_t)((c & 1) * 16384) + (uint32_t)(wk * 8192);
            const int blk = c * 2 + wk;
            const uint32_t bHb = sbase + RB_HI + (uint32_t)(blk * 2048);
            const uint32_t bLb = sbase + RB_LO + (uint32_t)(blk * 2048);

            #pragma unroll
            for (int ks2 = 0; ks2 < 2; ks2++) {
                uint32_t bH[4], bL[4];
                {
                    int row = wn * 8 + b_row;
                    int cu  = ks2 * 4 + b_cu4;
                    uint32_t off = SWZ128((uint32_t)(row * 128 + cu * 16));
                    LDSM4(bH, bHb + off);
                    LDSM4(bL, bLb + off);
                }
                #pragma unroll
                for (int ks = 0; ks < 2; ks++) {
                    uint32_t aF[2][4];
                    #pragma unroll
                    for (int mt = 0; mt < 2; mt++) {
                        int row = wm * 32 + mt * 16 + a_row;
                        int cu  = ks2 * 4 + ks * 2 + a_cuh;
                        uint32_t off = SWZ128((uint32_t)(row * 128 + cu * 16));
                        LDSM4(aF[mt], aB + off);
                    }
                    #pragma unroll
                    for (int mt = 0; mt < 2; mt++) {
                        MMAF16(accH[mt], aF[mt], bH[2 * ks], bH[2 * ks + 1]);
                        MMAF16(accL[mt], aF[mt], bL[2 * ks], bL[2 * ks + 1]);
                    }
                }
            }
            __syncthreads();
        }

        // ---- cross-k reduction via smem (A stage 0 region is free now) ----
        if (wk == 1) {
            #pragma unroll
            for (int mt = 0; mt < 2; mt++)
                #pragma unroll
                for (int q = 0; q < 4; q++)
                    red[((p * 2 + mt) * 4 + q) * 32 + lane] = accH[mt][q] + accL[mt][q];
        }
        __syncthreads();

        // ---- fused epilogue (warps 0-3): shuffle gate-quad exchange + LSTM ----
        if (w < 4) {
            #pragma unroll
            for (int mt = 0; mt < 2; mt++) {
                float v0 = accH[mt][0] + accL[mt][0] + red[((p * 2 + mt) * 4 + 0) * 32 + lane];
                float v1 = accH[mt][1] + accL[mt][1] + red[((p * 2 + mt) * 4 + 1) * 32 + lane];
                float v2 = accH[mt][2] + accL[mt][2] + red[((p * 2 + mt) * 4 + 2) * 32 + lane];
                float v3 = accH[mt][3] + accL[mt][3] + red[((p * 2 + mt) * 4 + 3) * 32 + lane];
                float e0 = __shfl_xor_sync(FULL, v0, 1);
                float e1 = __shfl_xor_sync(FULL, v1, 1);
                float e2 = __shfl_xor_sync(FULL, v2, 1);
                float e3 = __shfl_xor_sync(FULL, v3, 1);
                float pf = (odd ? e2 : v0) + xpv[mt].x;
                float pi = (odd ? e3 : v1) + xpv[mt].y;
                float po = (odd ? v2 : e0) + xpv[mt].z;
                float pc = (odd ? v3 : e1) + xpv[mt].w;
                float fg = 1.f / (1.f + expf(-pf));
                float ig = 1.f / (1.f + expf(-pi));
                float og = 1.f / (1.f + expf(-po));
                float ct = tanhf(pc);
                cv[mt] = fg * cv[mt] + ig * ct;
                float hnew = og * tanhf(cv[mt]);
                __half hhi, hlo;
                split_f16(hnew, hhi, hlo);
                size_t ho = (size_t)t * BH + (size_t)eb[mt] * H_ + ju;
                g_Hshi[ho] = hhi;
                g_Hslo[ho] = hlo;
            }
        }

        // ---- barrier: contention-free flags + CTA0 release (VOLATILE poll) ----
        __threadfence();
        __syncthreads();
        if (tid == 0)
            ((volatile unsigned*)g_arrive)[blockIdx.x] = (unsigned)(t + 1);
        if (blockIdx.x == 0) {
            if (tid < 32) {
                volatile unsigned* f = (volatile unsigned*)g_arrive;
                const unsigned g = (unsigned)(t + 1);
                for (;;) {
                    bool ok = true;
                    #pragma unroll
                    for (int q = 0; q < 8; q++)
                        if (f[lane + q * 32] < g) ok = false;
                    if (__all_sync(FULL, ok)) break;
                }
                __threadfence();
                if (lane == 0)
                    *((volatile unsigned*)&g_bar_gen) = (unsigned)(t + 1);
            }
        } else {
            if (tid == 0) {
                while (*((volatile unsigned*)&g_bar_gen) < (unsigned)(t + 1)) { }
            }
        }
        __syncthreads();
        __threadfence();
    }

    // write back cell state (warps 0-3 own it)
    if (w < 4) {
        #pragma unroll
        for (int mt = 0; mt < 2; mt++)
            g_c[eb[mt] * H_ + ju] = cv[mt];
    }
}

// ---------------- final h / c copy (hi+lo reconstruction) ----------------
__global__ void write_hc(float* __restrict__ dst)
{
    int i = blockIdx.x * blockDim.x + threadIdx.x;
    if (i < BH) {
        size_t o = (size_t)(T_ - 1) * BH + i;
        dst[i]      = __half2float(g_Hshi[o]) + __half2float(g_Hslo[o]);
        dst[BH + i] = g_c[i];
    }
}

// ---------------- launch ----------------
extern "C" void kernel_launch(void* const* d_in, const int* in_sizes, int n_in,
                              void* d_out, int out_size)
{
    const float* input_seq = (const float*)d_in[0];
    const float* hidden    = (const float*)d_in[1];
    const float* cell      = (const float*)d_in[2];
    const float* Wf        = (const float*)d_in[3];
    const float* bf        = (const float*)d_in[4];
    const float* Wi        = (const float*)d_in[5];
    const float* bi        = (const float*)d_in[6];
    const float* Wo        = (const float*)d_in[7];
    const float* bo        = (const float*)d_in[8];
    const float* Wc        = (const float*)d_in[9];
    const float* bc        = (const float*)d_in[10];
    const float* Wout      = (const float*)d_in[11];
    const float* bout      = (const float*)d_in[12];
    float* out = (float*)d_out;

    cudaFuncSetAttribute(gemm_f16_2t, cudaFuncAttributeMaxDynamicSharedMemorySize, GEMM_SMEM);
    cudaFuncSetAttribute(lstm_mma_persistent, cudaFuncAttributeMaxDynamicSharedMemorySize, REC_SMEM);

    float *pBias, *pX;
    __half *pXf, *pWxh, *pWxl, *pWoh, *pWol, *pHsh;
    cudaGetSymbolAddress((void**)&pBias, g_bias);
    cudaGetSymbolAddress((void**)&pX,    g_Xproj);
    cudaGetSymbolAddress((void**)&pXf,   g_Xf16);
    cudaGetSymbolAddress((void**)&pWxh,  g_WxThi);
    cudaGetSymbolAddress((void**)&pWxl,  g_WxTlo);
    cudaGetSymbolAddress((void**)&pWoh,  g_WoThi);
    cudaGetSymbolAddress((void**)&pWol,  g_WoTlo);
    cudaGetSymbolAddress((void**)&pHsh,  g_Hshi);

    // 1. packs + conversions
    pack_gates_t<<<48 * 32, 256>>>(Wf, Wi, Wo, Wc);
    pack_wout_t<<<32 * 8, 256>>>(Wout);
    {
        size_t n = (size_t)T_ * B_ * E_;
        convert_x<<<(int)((n + 255) / 256), 256>>>(input_seq, pXf, n);
    }
    init_state<<<(BH + 255) / 256, 256>>>(hidden, cell, bf, bi, bo, bc);

    // 2. Xproj = X @ WxT^T + bias  (M=32768, N=4096, K=512), fp16 2-term
    {
        dim3 grid(G4 / 128, (T_ * B_) / 128);
        gemm_f16_2t<<<grid, 256, GEMM_SMEM>>>(pXf, pWxh, pWxl, pBias, pX, E_, G4);
    }

    // 3. recurrence (persistent, 2 CTAs/SM, K-split warps)
    lstm_mma_persistent<<<NCTA_REC, 256, REC_SMEM>>>();

    // 4. out GEMM (M=32768, N=256, K=1024), fp16 2-term
    {
        dim3 grid(V_ / 128, (T_ * B_) / 128);
        gemm_f16_2t<<<grid, 256, GEMM_SMEM>>>(pHsh, pWoh, pWol, bout, out, H_, V_);
    }

    // 5. final h, c
    write_hc<<<(BH + 255) / 256, 256>>>(out + (size_t)T_ * B_ * V_);
}

// round 16
// speedup vs baseline: 1.1112x; 1.0877x over previous
#include <cuda_runtime.h>
#include <cuda_fp16.h>
#include <math.h>
#include <stdint.h>

// Problem dims
#define T_  512
#define B_  64
#define E_  512
#define H_  1024
#define V_  256
#define G4  4096   // 4*H gate-interleaved: col n = 4*j + g

#define NCTA_REC 128
#define BH  (B_ * H_)

// ---------------- scratch (device globals; allocation-free) ----------------
__device__ float g_bias[G4];
__device__ float g_Xproj[(size_t)T_ * B_ * G4];       // 512 MB
__device__ float g_c[B_ * H_];
__device__ __align__(16) unsigned g_arrive[NCTA_REC];
__device__ unsigned g_bar_gen;

// fp16 operands (16B aligned)
__device__ __align__(16) __half g_Xf16[(size_t)T_ * B_ * E_];   // input_seq fp16
__device__ __align__(16) __half g_WxThi[G4 * E_];               // WxT[n][k] hi
__device__ __align__(16) __half g_WxTlo[G4 * E_];               // WxT[n][k] lo
__device__ __align__(16) __half g_WhThi[G4 * H_];               // WhT[n][k] hi
__device__ __align__(16) __half g_WhTlo[G4 * H_];               // WhT[n][k] lo
__device__ __align__(16) __half g_WoThi[V_ * H_];               // WoT[v][k] hi
__device__ __align__(16) __half g_WoTlo[V_ * H_];               // WoT[v][k] lo
__device__ __align__(16) __half g_h0hi[BH];
__device__ __align__(16) __half g_h0lo[BH];
__device__ __align__(16) __half g_Hshi[(size_t)T_ * BH];        // h_t fp16 hi
__device__ __align__(16) __half g_Hslo[(size_t)T_ * BH];        // h_t fp16 lo

// ---------------- PTX helpers (plain-sm_100 legal) ----------------
__device__ __forceinline__ uint32_t smem_u32(const void* p) {
    uint32_t a;
    asm("{ .reg .u64 t; cvta.to.shared.u64 t, %1; cvt.u32.u64 %0, t; }" : "=r"(a) : "l"(p));
    return a;
}
#define SWZ128(o) ((o) ^ (((o) >> 3) & 0x70))

#define CP16(dst, src) \
    asm volatile("cp.async.cg.shared.global [%0], [%1], 16;" :: "r"(dst), "l"(src))
#define CP_COMMIT() asm volatile("cp.async.commit_group;" ::: "memory")
#define CP_WAIT2()  asm volatile("cp.async.wait_group 2;" ::: "memory")
#define CP_WAIT1()  asm volatile("cp.async.wait_group 1;" ::: "memory")
#define CP_WAIT0()  asm volatile("cp.async.wait_group 0;" ::: "memory")

#define LDSM4(r, addr) \
    asm volatile("ldmatrix.sync.aligned.m8n8.x4.shared.b16 {%0,%1,%2,%3}, [%4];" \
        : "=r"((r)[0]), "=r"((r)[1]), "=r"((r)[2]), "=r"((r)[3]) : "r"(addr))

#define MMAF16(c, a, b0, b1) \
    asm volatile("mma.sync.aligned.m16n8k16.row.col.f32.f16.f16.f32 " \
        "{%0,%1,%2,%3}, {%4,%5,%6,%7}, {%8,%9}, {%0,%1,%2,%3};" \
        : "+f"((c)[0]), "+f"((c)[1]), "+f"((c)[2]), "+f"((c)[3]) \
        : "r"((a)[0]), "r"((a)[1]), "r"((a)[2]), "r"((a)[3]), "r"(b0), "r"(b1))

__device__ __forceinline__ void split_f16(float v, __half& hi, __half& lo) {
    hi = __float2half_rn(v);
    lo = __float2half_rn(v - __half2float(hi));
}

// ---------------- packs: smem-tiled transposes (coalesced both sides) ----------------
__global__ __launch_bounds__(256) void pack_gates_t(
    const float* __restrict__ Wf, const float* __restrict__ Wi,
    const float* __restrict__ Wo, const float* __restrict__ Wc)
{
    __shared__ float tile[4][32][33];
    const int tid = threadIdx.x;
    const int jt  = blockIdx.x & 31;          // j tile (H/32 = 32)
    const int kt  = blockIdx.x >> 5;          // k tile ((E+H)/32 = 48)
    const int k0  = kt * 32, j0 = jt * 32;

    const float* W[4] = {Wf, Wi, Wo, Wc};
    #pragma unroll
    for (int g = 0; g < 4; g++)
        #pragma unroll
        for (int i = 0; i < 4; i++) {
            int u = tid + i * 256;
            int r = u >> 5, c = u & 31;
            tile[g][r][c] = W[g][(size_t)(k0 + r) * H_ + j0 + c];
        }
    __syncthreads();

    const bool isWx = (k0 < E_);
    const int kb = isWx ? k0 : (k0 - E_);
    const int K  = isWx ? E_ : H_;
    __half* Dh = isWx ? g_WxThi : g_WhThi;
    __half* Dl = isWx ? g_WxTlo : g_WhTlo;

    #pragma unroll
    for (int i = 0; i < 16; i++) {
        int rowu = (tid >> 5) + i * 8;        // 0..127 output rows within tile
        int g  = rowu & 3;
        int jj = rowu >> 2;
        int kk = tid & 31;
        float v = tile[g][kk][jj];
        __half hi, lo;
        split_f16(v, hi, lo);
        size_t o = (size_t)((j0 + jj) * 4 + g) * K + kb + kk;
        Dh[o] = hi;
        Dl[o] = lo;
    }
}

// Wout [H][V] row-major -> WoT[v][k]
__global__ __launch_bounds__(256) void pack_wout_t(const float* __restrict__ Wout)
{
    __shared__ float tile[32][33];
    const int tid = threadIdx.x;
    const int vt  = blockIdx.x & 7;           // V/32 = 8
    const int kt  = blockIdx.x >> 3;          // H/32 = 32
    const int k0  = kt * 32, v0 = vt * 32;

    #pragma unroll
    for (int i = 0; i < 4; i++) {
        int u = tid + i * 256;
        int r = u >> 5, c = u & 31;
        tile[r][c] = Wout[(size_t)(k0 + r) * V_ + v0 + c];
    }
    __syncthreads();

    #pragma unroll
    for (int i = 0; i < 4; i++) {
        int u = tid + i * 256;
        int vv = u >> 5, kk = u & 31;
        float val = tile[kk][vv];
        __half hi, lo;
        split_f16(val, hi, lo);
        size_t o = (size_t)(v0 + vv) * H_ + k0 + kk;
        g_WoThi[o] = hi;
        g_WoTlo[o] = lo;
    }
}

__global__ void convert_x(const float* __restrict__ src, __half* __restrict__ dst, size_t n)
{
    size_t i = (size_t)blockIdx.x * blockDim.x + threadIdx.x;
    if (i < n) dst[i] = __float2half_rn(src[i]);
}

// ---------------- init state (+ bias pack + barrier reset) ----------------
__global__ void init_state(const float* __restrict__ hidden, const float* __restrict__ cell,
                           const float* __restrict__ bf, const float* __restrict__ bi,
                           const float* __restrict__ bo, const float* __restrict__ bc)
{
    int i = blockIdx.x * blockDim.x + threadIdx.x;
    if (i < BH) {
        __half hi, lo;
        split_f16(hidden[i], hi, lo);
        g_h0hi[i] = hi;
        g_h0lo[i] = lo;
        g_c[i]    = cell[i];
    }
    if (i < H_) {
        g_bias[i * 4 + 0] = bf[i];
        g_bias[i * 4 + 1] = bi[i];
        g_bias[i * 4 + 2] = bo[i];
        g_bias[i * 4 + 3] = bc[i];
    }
    if (i < NCTA_REC) g_arrive[i] = 0;
    if (i == 0) g_bar_gen = 0;
}

// ---------------- fp16 2-term GEMM: C = A@Bhi^T + A@Blo^T + bias ----------------
#define STG2        49152     // A 16K | Bhi 16K | Blo 16K
#define O2_A        0
#define O2_BHI      16384
#define O2_BLO      32768
#define GEMM_SMEM   (2 * STG2)

__device__ __forceinline__ void stage_fill2(
    uint32_t sstage, const __half* __restrict__ A,
    const __half* __restrict__ Bhi, const __half* __restrict__ Blo,
    int m0, int n0, int kc, int K, int tid)
{
    #pragma unroll
    for (int i = 0; i < 4; i++) {             // A: 128 rows x 8 cu
        int u  = tid + i * 256;
        int r  = u >> 3;
        int cu = u & 7;
        uint32_t dsw = SWZ128((uint32_t)(r * 128 + cu * 16));
        CP16(sstage + O2_A + dsw, A + (size_t)(m0 + r) * K + kc + cu * 8);
    }
    #pragma unroll
    for (int i = 0; i < 4; i++) {             // B: 128 rows x 8 cu
        int u  = tid + i * 256;
        int r  = u >> 3;
        int cu = u & 7;
        uint32_t dsw = SWZ128((uint32_t)(r * 128 + cu * 16));
        size_t bo = (size_t)(n0 + r) * K + kc + cu * 8;
        CP16(sstage + O2_BHI + dsw, Bhi + bo);
        CP16(sstage + O2_BLO + dsw, Blo + bo);
    }
}

__global__ __launch_bounds__(256, 2) void gemm_f16_2t(
    const __half* __restrict__ A,
    const __half* __restrict__ Bhi, const __half* __restrict__ Blo,
    const float* __restrict__ bias, float* __restrict__ C,
    int K, int ldc)
{
    extern __shared__ char smem[];
    const uint32_t sbase = smem_u32(smem);
    const int tid  = threadIdx.x;
    const int lane = tid & 31;
    const int w    = tid >> 5;
    const int wm   = w & 3;          // m offset wm*32
    const int wn   = w >> 2;         // n offset wn*64
    const int m0 = blockIdx.y * 128;
    const int n0 = blockIdx.x * 128;
    const int NC = K / 64;

    float acc[2][8][4];
    #pragma unroll
    for (int mt = 0; mt < 2; mt++)
        #pragma unroll
        for (int nt = 0; nt < 8; nt++)
            #pragma unroll
            for (int q = 0; q < 4; q++) acc[mt][nt][q] = 0.f;

    stage_fill2(sbase, A, Bhi, Blo, m0, n0, 0, K, tid);
    CP_COMMIT();

    const int a_row = (lane & 15);
    const int a_cuh = (lane >> 4);
    const int b_row = (lane & 7) + ((lane >> 4) << 3);
    const int b_cuh = ((lane >> 3) & 1);

    #pragma unroll 1
    for (int c = 0; c < NC; c++) {
        if (c + 1 < NC) {
            stage_fill2(sbase + ((c + 1) & 1) * STG2, A, Bhi, Blo,
                        m0, n0, (c + 1) * 64, K, tid);
            CP_COMMIT();
            CP_WAIT1();
        } else {
            CP_WAIT0();
        }
        __syncthreads();

        const uint32_t sS = sbase + (c & 1) * STG2;

        #pragma unroll
        for (int ks = 0; ks < 4; ks++) {
            uint32_t aF[2][4];
            #pragma unroll
            for (int mt = 0; mt < 2; mt++) {
                int row = wm * 32 + mt * 16 + a_row;
                int cu  = ks * 2 + a_cuh;
                uint32_t off = SWZ128((uint32_t)(row * 128 + cu * 16));
                LDSM4(aF[mt], sS + O2_A + off);
            }
            #pragma unroll
            for (int nh = 0; nh < 2; nh++) {
                uint32_t bH[2][4], bL[2][4];
                #pragma unroll
                for (int p = 0; p < 2; p++) {
                    int np = nh * 2 + p;
                    int row = wn * 64 + np * 16 + b_row;
                    int cu  = ks * 2 + b_cuh;
                    uint32_t off = SWZ128((uint32_t)(row * 128 + cu * 16));
                    LDSM4(bH[p], sS + O2_BHI + off);
                    LDSM4(bL[p], sS + O2_BLO + off);
                }
                #pragma unroll
                for (int mt = 0; mt < 2; mt++)
                    #pragma unroll
                    for (int p = 0; p < 2; p++) {
                        int np = nh * 2 + p;
                        MMAF16(acc[mt][2 * np],     aF[mt], bH[p][0], bH[p][1]);
                        MMAF16(acc[mt][2 * np + 1], aF[mt], bH[p][2], bH[p][3]);
                        MMAF16(acc[mt][2 * np],     aF[mt], bL[p][0], bL[p][1]);
                        MMAF16(acc[mt][2 * np + 1], aF[mt], bL[p][2], bL[p][3]);
                    }
            }
        }
        __syncthreads();
    }

    #pragma unroll
    for (int mt = 0; mt < 2; mt++) {
        int rbase = m0 + wm * 32 + mt * 16 + (lane >> 2);
        #pragma unroll
        for (int nt = 0; nt < 8; nt++) {
            int col = n0 + wn * 64 + nt * 8 + (lane & 3) * 2;
            float2 bv = *(const float2*)&bias[col];
            float2 v0, v1;
            v0.x = acc[mt][nt][0] + bv.x;
            v0.y = acc[mt][nt][1] + bv.y;
            v1.x = acc[mt][nt][2] + bv.x;
            v1.y = acc[mt][nt][3] + bv.y;
            *(float2*)&C[(size_t)rbase * ldc + col]       = v0;
            *(float2*)&C[(size_t)(rbase + 8) * ldc + col] = v1;
        }
    }
}

// ---------------- persistent tensor-core LSTM recurrence ----------------
// Round-11 structure (128 CTAs, 32 gate-cols, Wh 128 KB resident, shuffle epilogue)
// with: 4-stage A pipeline + ONE sync per chunk, flag barrier.
#define RB_HI       0                    // 64 KB  Wh hi: 16 blocks of 32x64
#define RB_LO       65536                // 64 KB  Wh lo
#define RA_BASE     131072               // 4 x 16 KB A stages
#define REC_SMEM    196608               // 192 KB

__global__ __launch_bounds__(256, 1) void lstm_mma_persistent()
{
    extern __shared__ char smem[];
    const uint32_t sbase = smem_u32(smem);

    const int tid  = threadIdx.x;
    const int lane = tid & 31;
    const int w    = tid >> 5;
    const int wm   = w & 1;          // m offset wm*32
    const int wn   = w >> 1;         // n offset wn*8 (0..3)
    const int n0   = blockIdx.x * 32;

    const int a_row = (lane & 15);
    const int a_cuh = (lane >> 4);
    const int b_row = (lane & 7);
    const int b_cu4 = ((lane >> 3) & 3);

    // ---- load resident Wh tile (once) ----
    {
        int r = tid >> 3, cu = tid & 7;      // 256 threads = 32 rows x 8 cu
        uint32_t dswb = SWZ128((uint32_t)(r * 128 + cu * 16));
        #pragma unroll
        for (int blk = 0; blk < 16; blk++) {
            uint32_t d = (uint32_t)(blk * 4096) + dswb;
            size_t src = (size_t)(n0 + r) * H_ + blk * 64 + cu * 8;
            CP16(sbase + RB_HI + d, g_WhThi + src);
            CP16(sbase + RB_LO + d, g_WhTlo + src);
        }
    }
    CP_COMMIT();
    CP_WAIT0();
    __syncthreads();

    // epilogue ownership (fixed across steps)
    const int odd = lane & 1;
    const int ju  = (n0 >> 2) + wn * 2 + ((lane & 3) >> 1);   // hidden unit
    int eb[2];
    float cv[2];
    #pragma unroll
    for (int mt = 0; mt < 2; mt++) {
        eb[mt] = wm * 32 + mt * 16 + (lane >> 2) + (odd ? 8 : 0);
        cv[mt] = g_c[eb[mt] * H_ + ju];
    }
    const unsigned FULL = 0xffffffffu;

    for (int t = 0; t < T_; t++) {
        const __half* A_t = (t == 0) ? g_h0hi : g_Hshi + (size_t)(t - 1) * BH;
        const float* xp_t = g_Xproj + (size_t)t * B_ * G4;

        // prefetch per-step epilogue operands (hidden under mainloop)
        float4 xpv[2];
        #pragma unroll
        for (int mt = 0; mt < 2; mt++)
            xpv[mt] = *(const float4*)&xp_t[(size_t)eb[mt] * G4 + ju * 4];

        float accH[2][4], accL[2][4];
        #pragma unroll
        for (int mt = 0; mt < 2; mt++)
            #pragma unroll
            for (int q = 0; q < 4; q++) { accH[mt][q] = 0.f; accL[mt][q] = 0.f; }

        // ---- prologue: issue chunks 0,1,2 (3 commit groups) ----
        #pragma unroll
        for (int pc = 0; pc < 3; pc++) {
            uint32_t dstb = sbase + RA_BASE + (uint32_t)(pc * 16384);
            #pragma unroll
            for (int i = 0; i < 4; i++) {
                int u = tid + i * 256;
                int s = u >> 9;
                int rem = u & 511;
                int r = rem >> 3, cu = rem & 7;
                uint32_t dsw = (uint32_t)(s * 8192) + SWZ128((uint32_t)(r * 128 + cu * 16));
                CP16(dstb + dsw, A_t + (size_t)r * H_ + pc * 128 + s * 64 + cu * 8);
            }
            CP_COMMIT();
        }

        // ---- main loop: ONE sync per chunk, 3-deep prefetch ----
        #pragma unroll 1
        for (int c = 0; c < 8; c++) {
            if (c < 6)      CP_WAIT2();
            else if (c == 6) CP_WAIT1();
            else             CP_WAIT0();
            __syncthreads();   // chunk c visible to all; stage (c+3)&3 consumed by all

            if (c + 3 < 8) {
                uint32_t dstb = sbase + RA_BASE + (uint32_t)(((c + 3) & 3) * 16384);
                int kc = (c + 3) * 128;
                #pragma unroll
                for (int i = 0; i < 4; i++) {
                    int u = tid + i * 256;
                    int s = u >> 9;
                    int rem = u & 511;
                    int r = rem >> 3, cu = rem & 7;
                    uint32_t dsw = (uint32_t)(s * 8192) + SWZ128((uint32_t)(r * 128 + cu * 16));
                    CP16(dstb + dsw, A_t + (size_t)r * H_ + kc + s * 64 + cu * 8);
                }
                CP_COMMIT();
            }

            const uint32_t sA = sbase + RA_BASE + (uint32_t)((c & 3) * 16384);

            #pragma unroll
            for (int s = 0; s < 2; s++) {
                const int blk = c * 2 + s;
                const uint32_t bHb = sbase + RB_HI + (uint32_t)(blk * 4096);
                const uint32_t bLb = sbase + RB_LO + (uint32_t)(blk * 4096);
                const uint32_t aB  = sA + (uint32_t)(s * 8192);

                #pragma unroll
                for (int ks2 = 0; ks2 < 2; ks2++) {
                    uint32_t bH[4], bL[4];
                    {
                        int row = wn * 8 + b_row;
                        int cu  = ks2 * 4 + b_cu4;
                        uint32_t off = SWZ128((uint32_t)(row * 128 + cu * 16));
                        LDSM4(bH, bHb + off);
                        LDSM4(bL, bLb + off);
                    }
                    #pragma unroll
                    for (int ks = 0; ks < 2; ks++) {
                        uint32_t aF[2][4];
                        #pragma unroll
                        for (int mt = 0; mt < 2; mt++) {
                            int row = wm * 32 + mt * 16 + a_row;
                            int cu  = ks2 * 4 + ks * 2 + a_cuh;
                            uint32_t off = SWZ128((uint32_t)(row * 128 + cu * 16));
                            LDSM4(aF[mt], aB + off);
                        }
                        #pragma unroll
                        for (int mt = 0; mt < 2; mt++) {
                            MMAF16(accH[mt], aF[mt], bH[2 * ks], bH[2 * ks + 1]);
                            MMAF16(accL[mt], aF[mt], bL[2 * ks], bL[2 * ks + 1]);
                        }
                    }
                }
            }
        }

        // ---- fused epilogue: shuffle gate-quad exchange + LSTM pointwise ----
        #pragma unroll
        for (int mt = 0; mt < 2; mt++) {
            float v0 = accH[mt][0] + accL[mt][0];
            float v1 = accH[mt][1] + accL[mt][1];
            float v2 = accH[mt][2] + accL[mt][2];
            float v3 = accH[mt][3] + accL[mt][3];
            float e0 = __shfl_xor_sync(FULL, v0, 1);
            float e1 = __shfl_xor_sync(FULL, v1, 1);
            float e2 = __shfl_xor_sync(FULL, v2, 1);
            float e3 = __shfl_xor_sync(FULL, v3, 1);
            float pf = (odd ? e2 : v0) + xpv[mt].x;
            float pi = (odd ? e3 : v1) + xpv[mt].y;
            float po = (odd ? v2 : e0) + xpv[mt].z;
            float pc = (odd ? v3 : e1) + xpv[mt].w;
            float fg = 1.f / (1.f + expf(-pf));
            float ig = 1.f / (1.f + expf(-pi));
            float og = 1.f / (1.f + expf(-po));
            float ct = tanhf(pc);
            cv[mt] = fg * cv[mt] + ig * ct;
            float hnew = og * tanhf(cv[mt]);
            __half hhi, hlo;
            split_f16(hnew, hhi, hlo);
            size_t ho = (size_t)t * BH + (size_t)eb[mt] * H_ + ju;
            g_Hshi[ho] = hhi;
            g_Hslo[ho] = hlo;
        }

        // ---- barrier: contention-free flags + CTA0 release (volatile poll) ----
        __threadfence();
        __syncthreads();
        if (tid == 0)
            ((volatile unsigned*)g_arrive)[blockIdx.x] = (unsigned)(t + 1);
        if (blockIdx.x == 0) {
            if (tid < 32) {
                volatile unsigned* f = (volatile unsigned*)g_arrive;
                const unsigned g = (unsigned)(t + 1);
                for (;;) {
                    bool ok = true;
                    #pragma unroll
                    for (int q = 0; q < 4; q++)
                        if (f[lane + q * 32] < g) ok = false;
                    if (__all_sync(FULL, ok)) break;
                }
                __threadfence();
                if (lane == 0)
                    *((volatile unsigned*)&g_bar_gen) = (unsigned)(t + 1);
            }
        } else {
            if (tid == 0) {
                while (*((volatile unsigned*)&g_bar_gen) < (unsigned)(t + 1)) { }
            }
        }
        __syncthreads();
        __threadfence();
    }

    // write back cell state
    #pragma unroll
    for (int mt = 0; mt < 2; mt++)
        g_c[eb[mt] * H_ + ju] = cv[mt];
}

// ---------------- final h / c copy (hi+lo reconstruction) ----------------
__global__ void write_hc(float* __restrict__ dst)
{
    int i = blockIdx.x * blockDim.x + threadIdx.x;
    if (i < BH) {
        size_t o = (size_t)(T_ - 1) * BH + i;
        dst[i]      = __half2float(g_Hshi[o]) + __half2float(g_Hslo[o]);
        dst[BH + i] = g_c[i];
    }
}

// ---------------- launch ----------------
extern "C" void kernel_launch(void* const* d_in, const int* in_sizes, int n_in,
                              void* d_out, int out_size)
{
    const float* input_seq = (const float*)d_in[0];
    const float* hidden    = (const float*)d_in[1];
    const float* cell      = (const float*)d_in[2];
    const float* Wf        = (const float*)d_in[3];
    const float* bf        = (const float*)d_in[4];
    const float* Wi        = (const float*)d_in[5];
    const float* bi        = (const float*)d_in[6];
    const float* Wo        = (const float*)d_in[7];
    const float* bo        = (const float*)d_in[8];
    const float* Wc        = (const float*)d_in[9];
    const float* bc        = (const float*)d_in[10];
    const float* Wout      = (const float*)d_in[11];
    const float* bout      = (const float*)d_in[12];
    float* out = (float*)d_out;

    cudaFuncSetAttribute(gemm_f16_2t, cudaFuncAttributeMaxDynamicSharedMemorySize, GEMM_SMEM);
    cudaFuncSetAttribute(lstm_mma_persistent, cudaFuncAttributeMaxDynamicSharedMemorySize, REC_SMEM);

    float *pBias, *pX;
    __half *pXf, *pWxh, *pWxl, *pWoh, *pWol, *pHsh;
    cudaGetSymbolAddress((void**)&pBias, g_bias);
    cudaGetSymbolAddress((void**)&pX,    g_Xproj);
    cudaGetSymbolAddress((void**)&pXf,   g_Xf16);
    cudaGetSymbolAddress((void**)&pWxh,  g_WxThi);
    cudaGetSymbolAddress((void**)&pWxl,  g_WxTlo);
    cudaGetSymbolAddress((void**)&pWoh,  g_WoThi);
    cudaGetSymbolAddress((void**)&pWol,  g_WoTlo);
    cudaGetSymbolAddress((void**)&pHsh,  g_Hshi);

    // 1. packs + conversions
    pack_gates_t<<<48 * 32, 256>>>(Wf, Wi, Wo, Wc);
    pack_wout_t<<<32 * 8, 256>>>(Wout);
    {
        size_t n = (size_t)T_ * B_ * E_;
        convert_x<<<(int)((n + 255) / 256), 256>>>(input_seq, pXf, n);
    }
    init_state<<<(BH + 255) / 256, 256>>>(hidden, cell, bf, bi, bo, bc);

    // 2. Xproj = X @ WxT^T + bias  (M=32768, N=4096, K=512), fp16 2-term
    {
        dim3 grid(G4 / 128, (T_ * B_) / 128);
        gemm_f16_2t<<<grid, 256, GEMM_SMEM>>>(pXf, pWxh, pWxl, pBias, pX, E_, G4);
    }

    // 3. recurrence (persistent, 128 CTAs, 4-stage pipeline, flag barrier)
    lstm_mma_persistent<<<NCTA_REC, 256, REC_SMEM>>>();

    // 4. out GEMM (M=32768, N=256, K=1024), fp16 2-term
    {
        dim3 grid(V_ / 128, (T_ * B_) / 128);
        gemm_f16_2t<<<grid, 256, GEMM_SMEM>>>(pHsh, pWoh, pWol, bout, out, H_, V_);
    }

    // 5. final h, c
    write_hc<<<(BH + 255) / 256, 256>>>(out + (size_t)T_ * B_ * V_);
}